// round 2
// baseline (speedup 1.0000x reference)
#include <cuda_runtime.h>
#include <cuda_bf16.h>
#include <stdint.h>

#define BB   8
#define CCH  128
#define NN   4096
#define DD   16
#define NCO  160

#define XS_STRIDE 136
#define WS_STRIDE 136
#define VS_STRIDE 136
#define KS_STRIDE 24
#define KS_BUF_ELEMS (128*KS_STRIDE)
#define VS_BUF_ELEMS (128*VS_STRIDE)

__device__ __nv_bfloat16 g_Q[(size_t)BB*NN*DD];
__device__ __nv_bfloat16 g_K[(size_t)BB*NN*DD];
__device__ __nv_bfloat16 g_V[(size_t)BB*NN*CCH];

__device__ __forceinline__ uint32_t smem_u32(const void* p){
  return (uint32_t)__cvta_generic_to_shared(p);
}
__device__ __forceinline__ void mma_bf16(float &c0,float &c1,float &c2,float &c3,
    uint32_t a0,uint32_t a1,uint32_t a2,uint32_t a3,uint32_t b0,uint32_t b1){
  asm volatile("mma.sync.aligned.m16n8k16.row.col.f32.bf16.bf16.f32 "
    "{%0,%1,%2,%3}, {%4,%5,%6,%7}, {%8,%9}, {%0,%1,%2,%3};\n"
    : "+f"(c0),"+f"(c1),"+f"(c2),"+f"(c3)
    : "r"(a0),"r"(a1),"r"(a2),"r"(a3),"r"(b0),"r"(b1));
}
__device__ __forceinline__ void ldsm_x4_t(uint32_t &r0,uint32_t &r1,uint32_t &r2,uint32_t &r3,uint32_t addr){
  asm volatile("ldmatrix.sync.aligned.m8n8.x4.trans.shared.b16 {%0,%1,%2,%3}, [%4];\n"
   : "=r"(r0),"=r"(r1),"=r"(r2),"=r"(r3) : "r"(addr));
}
__device__ __forceinline__ void cp_async16(uint32_t dst, const void* src){
  asm volatile("cp.async.cg.shared.global [%0], [%1], 16;\n" :: "r"(dst), "l"(src));
}
__device__ __forceinline__ float fast_exp2(float xx){
  float y; asm("ex2.approx.ftz.f32 %0, %1;" : "=f"(y) : "f"(xx)); return y;
}
__device__ __forceinline__ uint32_t pack_bf162(float lo, float hi){
  uint32_t r; asm("cvt.rn.bf16x2.f32 %0, %1, %2;" : "=r"(r) : "f"(hi), "f"(lo)); return r;
}

// ---------------- Kernel 1: fused QKV projection ----------------
__global__ void __launch_bounds__(256, 1) qkv_proj_kernel(
    const float* __restrict__ x,
    const float* __restrict__ qw, const float* __restrict__ qb,
    const float* __restrict__ kw, const float* __restrict__ kb,
    const float* __restrict__ vw, const float* __restrict__ vb)
{
  extern __shared__ char smem[];
  __nv_bfloat16* Xs = (__nv_bfloat16*)smem;                       // [128 c][136]
  __nv_bfloat16* Ws = (__nv_bfloat16*)(smem + 128*XS_STRIDE*2);   // [160 co][136]
  float* bias_s     = (float*)(smem + 128*XS_STRIDE*2 + NCO*WS_STRIDE*2);

  const int tid  = threadIdx.x;
  const int b    = blockIdx.x >> 5;
  const int n0   = (blockIdx.x & 31) << 7;
  const int lane = tid & 31;
  const int warp = tid >> 5;
  const int qd   = lane & 3, rr = lane >> 2;

  for (int idx = tid; idx < NCO*CCH; idx += 256){
    int row = idx >> 7, c = idx & 127;
    float v;
    if (row < 16)      v = qw[row*CCH + c];
    else if (row < 32) v = kw[(row-16)*CCH + c];
    else               v = vw[(row-32)*CCH + c];
    Ws[row*WS_STRIDE + c] = __float2bfloat16(v);
  }
  if (tid < NCO)
    bias_s[tid] = (tid < 16) ? qb[tid] : (tid < 32) ? kb[tid-16] : vb[tid-32];

  { // Xs[c][j] = x[b][c][n0+j]
    int c = tid >> 1, half = tid & 1;
    const float4* src = (const float4*)(x + ((size_t)b*CCH + c)*NN + n0 + half*64);
    __nv_bfloat16* dst = Xs + c*XS_STRIDE + half*64;
    #pragma unroll
    for (int jj = 0; jj < 16; jj++){
      float4 v = src[jj];
      dst[jj*4+0] = __float2bfloat16(v.x);
      dst[jj*4+1] = __float2bfloat16(v.y);
      dst[jj*4+2] = __float2bfloat16(v.z);
      dst[jj*4+3] = __float2bfloat16(v.w);
    }
  }
  __syncthreads();

  const int m0 = warp << 4;
  uint32_t a[8][4];
  {
    int krow = (lane & 7) + ((lane & 16) ? 8 : 0);
    int mcol = m0 + ((lane & 8) ? 8 : 0);
    #pragma unroll
    for (int kc = 0; kc < 8; kc++){
      uint32_t addr = smem_u32(Xs + (kc*16 + krow)*XS_STRIDE + mcol);
      ldsm_x4_t(a[kc][0], a[kc][1], a[kc][2], a[kc][3], addr);
    }
  }

  float acc[20][4];
  #pragma unroll
  for (int t = 0; t < 20; t++){ acc[t][0]=0.f; acc[t][1]=0.f; acc[t][2]=0.f; acc[t][3]=0.f; }

  #pragma unroll
  for (int ct = 0; ct < 20; ct++){
    const __nv_bfloat16* wrow = Ws + (ct*8 + rr)*WS_STRIDE;
    #pragma unroll
    for (int kc = 0; kc < 8; kc++){
      uint32_t b0 = *(const uint32_t*)(wrow + kc*16 + 2*qd);
      uint32_t b1 = *(const uint32_t*)(wrow + kc*16 + 2*qd + 8);
      mma_bf16(acc[ct][0],acc[ct][1],acc[ct][2],acc[ct][3],
               a[kc][0],a[kc][1],a[kc][2],a[kc][3], b0, b1);
    }
  }

  const float LOG2E = 1.4426950408889634f;
  const int n1 = n0 + m0 + rr;
  #pragma unroll
  for (int ct = 0; ct < 20; ct++){
    int co = ct*8 + 2*qd;
    float b0v = bias_s[co], b1v = bias_s[co+1];
    float v00 = acc[ct][0] + b0v, v01 = acc[ct][1] + b1v;
    float v10 = acc[ct][2] + b0v, v11 = acc[ct][3] + b1v;
    if (co < 16){ v00*=LOG2E; v01*=LOG2E; v10*=LOG2E; v11*=LOG2E; }
    uint32_t p0 = pack_bf162(v00, v01);
    uint32_t p1 = pack_bf162(v10, v11);
    if (co < 16){
      *(uint32_t*)(g_Q + ((size_t)b*NN + n1    )*DD + co) = p0;
      *(uint32_t*)(g_Q + ((size_t)b*NN + n1 + 8)*DD + co) = p1;
    } else if (co < 32){
      *(uint32_t*)(g_K + ((size_t)b*NN + n1    )*DD + (co-16)) = p0;
      *(uint32_t*)(g_K + ((size_t)b*NN + n1 + 8)*DD + (co-16)) = p1;
    } else {
      *(uint32_t*)(g_V + ((size_t)b*NN + n1    )*CCH + (co-32)) = p0;
      *(uint32_t*)(g_V + ((size_t)b*NN + n1 + 8)*CCH + (co-32)) = p1;
    }
  }
}

// ---------------- Kernel 2: flash attention ----------------
__global__ void __launch_bounds__(256, 1) attn_kernel(
    const float* __restrict__ x, const float* __restrict__ gamma_p,
    float* __restrict__ out)
{
  extern __shared__ char smem[];
  __nv_bfloat16* Ks = (__nv_bfloat16*)smem;                     // 2 x [128][24]

  const int tid  = threadIdx.x;
  const int b    = blockIdx.x >> 5;
  const int n0   = (blockIdx.x & 31) << 7;
  const int lane = tid & 31;
  const int warp = tid >> 5;
  const int qd   = lane & 3, rr = lane >> 2;
  const int m0   = warp << 4;

  uint32_t qa[4];
  {
    const __nv_bfloat16* base = g_Q + ((size_t)b*NN + n0 + m0)*DD;
    qa[0] = *(const uint32_t*)(base + (rr  )*DD + 2*qd);
    qa[1] = *(const uint32_t*)(base + (rr+8)*DD + 2*qd);
    qa[2] = *(const uint32_t*)(base + (rr  )*DD + 2*qd + 8);
    qa[3] = *(const uint32_t*)(base + (rr+8)*DD + 2*qd + 8);
  }

  float o[16][4];
  #pragma unroll
  for (int t = 0; t < 16; t++){ o[t][0]=0.f; o[t][1]=0.f; o[t][2]=0.f; o[t][3]=0.f; }
  float mrun0 = -1e30f, mrun1 = -1e30f, l0 = 0.f, l1 = 0.f;

  const uint32_t kbase = smem_u32(smem);
  const uint32_t vbase = smem_u32(smem + 2*KS_BUF_ELEMS*2);

  { // prefetch chunk 0 -> buffer 0
    int row = tid >> 1, seg = tid & 1;
    cp_async16(kbase + row*(KS_STRIDE*2) + seg*16,
               g_K + ((size_t)b*NN + row)*DD + seg*8);
    #pragma unroll
    for (int i = 0; i < 8; i++){
      int id = tid + 256*i;
      int vr = id >> 4, sg = id & 15;
      cp_async16(vbase + vr*(VS_STRIDE*2) + sg*16,
                 g_V + ((size_t)b*NN + vr)*CCH + sg*8);
    }
  }
  asm volatile("cp.async.commit_group;\n" ::: "memory");

  const int vrow = lane & 15;
  const int vcol = (lane >> 4) * 8;

  for (int it = 0; it < 32; it++){
    const int buf = it & 1;

    if (it + 1 < 32){
      const int nb = buf ^ 1;
      const int kk0 = (it + 1) << 7;
      int row = tid >> 1, seg = tid & 1;
      cp_async16(kbase + nb*(KS_BUF_ELEMS*2) + row*(KS_STRIDE*2) + seg*16,
                 g_K + ((size_t)b*NN + kk0 + row)*DD + seg*8);
      #pragma unroll
      for (int i = 0; i < 8; i++){
        int id = tid + 256*i;
        int vr = id >> 4, sg = id & 15;
        cp_async16(vbase + nb*(VS_BUF_ELEMS*2) + vr*(VS_STRIDE*2) + sg*16,
                   g_V + ((size_t)b*NN + kk0 + vr)*CCH + sg*8);
      }
    }
    asm volatile("cp.async.commit_group;\n" ::: "memory");
    asm volatile("cp.async.wait_group 1;\n" ::: "memory");
    __syncthreads();

    // S = Q K^T (exp2 domain)
    const __nv_bfloat16* ksb = Ks + buf*KS_BUF_ELEMS;
    float s[16][4];
    #pragma unroll
    for (int t = 0; t < 16; t++){
      uint32_t kb0 = *(const uint32_t*)(ksb + (t*8 + rr)*KS_STRIDE + 2*qd);
      uint32_t kb1 = *(const uint32_t*)(ksb + (t*8 + rr)*KS_STRIDE + 2*qd + 8);
      s[t][0]=0.f; s[t][1]=0.f; s[t][2]=0.f; s[t][3]=0.f;
      mma_bf16(s[t][0],s[t][1],s[t][2],s[t][3], qa[0],qa[1],qa[2],qa[3], kb0,kb1);
    }

    // online softmax
    float mx0 = -1e30f, mx1 = -1e30f;
    #pragma unroll
    for (int t = 0; t < 16; t++){
      mx0 = fmaxf(mx0, fmaxf(s[t][0], s[t][1]));
      mx1 = fmaxf(mx1, fmaxf(s[t][2], s[t][3]));
    }
    mx0 = fmaxf(mx0, __shfl_xor_sync(0xffffffffu, mx0, 1));
    mx0 = fmaxf(mx0, __shfl_xor_sync(0xffffffffu, mx0, 2));
    mx1 = fmaxf(mx1, __shfl_xor_sync(0xffffffffu, mx1, 1));
    mx1 = fmaxf(mx1, __shfl_xor_sync(0xffffffffu, mx1, 2));
    float nm0 = fmaxf(mrun0, mx0), nm1 = fmaxf(mrun1, mx1);
    float sc0 = fast_exp2(mrun0 - nm0), sc1 = fast_exp2(mrun1 - nm1);
    mrun0 = nm0; mrun1 = nm1;

    float sum0 = 0.f, sum1 = 0.f;
    #pragma unroll
    for (int t = 0; t < 16; t++){
      s[t][0] = fast_exp2(s[t][0] - nm0); sum0 += s[t][0];
      s[t][1] = fast_exp2(s[t][1] - nm0); sum0 += s[t][1];
      s[t][2] = fast_exp2(s[t][2] - nm1); sum1 += s[t][2];
      s[t][3] = fast_exp2(s[t][3] - nm1); sum1 += s[t][3];
    }
    l0 = l0*sc0 + sum0;
    l1 = l1*sc1 + sum1;
    #pragma unroll
    for (int t = 0; t < 16; t++){
      o[t][0]*=sc0; o[t][1]*=sc0; o[t][2]*=sc1; o[t][3]*=sc1;
    }

    // O += P V   (P D-frags -> A-frags in registers)
    const uint32_t vtile = vbase + buf*(VS_BUF_ELEMS*2) + vrow*(VS_STRIDE*2) + vcol*2;
    #pragma unroll
    for (int kc = 0; kc < 8; kc++){
      uint32_t pa0 = pack_bf162(s[2*kc  ][0], s[2*kc  ][1]);
      uint32_t pa1 = pack_bf162(s[2*kc  ][2], s[2*kc  ][3]);
      uint32_t pa2 = pack_bf162(s[2*kc+1][0], s[2*kc+1][1]);
      uint32_t pa3 = pack_bf162(s[2*kc+1][2], s[2*kc+1][3]);
      #pragma unroll
      for (int nt = 0; nt < 8; nt++){
        uint32_t v0,v1,v2,v3;
        ldsm_x4_t(v0,v1,v2,v3, vtile + kc*16*(VS_STRIDE*2) + nt*16*2);
        mma_bf16(o[2*nt  ][0],o[2*nt  ][1],o[2*nt  ][2],o[2*nt  ][3], pa0,pa1,pa2,pa3, v0,v1);
        mma_bf16(o[2*nt+1][0],o[2*nt+1][1],o[2*nt+1][2],o[2*nt+1][3], pa0,pa1,pa2,pa3, v2,v3);
      }
    }
    __syncthreads();
  }

  // epilogue: out = gamma/l * O + x
  l0 += __shfl_xor_sync(0xffffffffu, l0, 1);
  l0 += __shfl_xor_sync(0xffffffffu, l0, 2);
  l1 += __shfl_xor_sync(0xffffffffu, l1, 1);
  l1 += __shfl_xor_sync(0xffffffffu, l1, 2);
  float g = *gamma_p;
  float inv0 = g / l0, inv1 = g / l1;
  const int na = n0 + m0 + rr, nb2 = na + 8;
  #pragma unroll
  for (int t = 0; t < 16; t++){
    int c0 = t*8 + 2*qd;
    size_t i00 = ((size_t)b*CCH + c0  )*NN + na;
    size_t i01 = ((size_t)b*CCH + c0+1)*NN + na;
    size_t i10 = ((size_t)b*CCH + c0  )*NN + nb2;
    size_t i11 = ((size_t)b*CCH + c0+1)*NN + nb2;
    out[i00] = o[t][0]*inv0 + x[i00];
    out[i01] = o[t][1]*inv0 + x[i01];
    out[i10] = o[t][2]*inv1 + x[i10];
    out[i11] = o[t][3]*inv1 + x[i11];
  }
}

extern "C" void kernel_launch(void* const* d_in, const int* in_sizes, int n_in,
                              void* d_out, int out_size) {
  const float* x  = (const float*)d_in[0];
  const float* qw = (const float*)d_in[1];
  const float* qb = (const float*)d_in[2];
  const float* kw = (const float*)d_in[3];
  const float* kb = (const float*)d_in[4];
  const float* vw = (const float*)d_in[5];
  const float* vb = (const float*)d_in[6];
  const float* gm = (const float*)d_in[7];
  float* out = (float*)d_out;

  const int proj_smem = 128*XS_STRIDE*2 + NCO*WS_STRIDE*2 + NCO*4;
  const int attn_smem = 2*KS_BUF_ELEMS*2 + 2*VS_BUF_ELEMS*2;
  cudaFuncSetAttribute(qkv_proj_kernel, cudaFuncAttributeMaxDynamicSharedMemorySize, proj_smem);
  cudaFuncSetAttribute(attn_kernel,     cudaFuncAttributeMaxDynamicSharedMemorySize, attn_smem);

  qkv_proj_kernel<<<BB*32, 256, proj_smem>>>(x, qw, qb, kw, kb, vw, vb);
  attn_kernel<<<BB*32, 256, attn_smem>>>(x, gm, out);
}